// round 4
// baseline (speedup 1.0000x reference)
#include <cuda_runtime.h>
#include <cuda_bf16.h>

// BalancedBCE fused single-kernel, round 3.
//
// Math per element (t in {0,1}):
//   bce = relu(x) - x*t + l,  l = log(1 + exp(-|x|))
//   pos part (t=1): relu(x)-x = relu(-x)  ->  sp = Σ t*relu(-x) + Σ_pos l
//   neg part (t=0):                          sn = Σ relu(x) - Σ t*relu(x) + Σ_neg l
// Grouped-log: Σ_pos l over a group = log( Π (1 + t*e) ),  e = exp(-|x|);
//              Σ_neg l             = log( Π (1 + (1-t)*e) ).
// One LG2 per 8 elements per class instead of one per element -> MUFU 2/elem -> 1.25/elem.

#define BATCH   64
#define BPB     32      // blocks per batch sample
#define THREADS 256
#define NBLOCKS (BATCH * BPB)   // 2048

// layout: g_part[blk*192 + qty*64 + b], qty: 0=S_pos 1=S_neg 2=count
__device__ float g_part[NBLOCKS * 3];
__device__ unsigned int g_ticket = 0;

__device__ __forceinline__ void block_reduce3(float& a, float& b, float& c) {
    #pragma unroll
    for (int off = 16; off > 0; off >>= 1) {
        a += __shfl_down_sync(0xFFFFFFFFu, a, off);
        b += __shfl_down_sync(0xFFFFFFFFu, b, off);
        c += __shfl_down_sync(0xFFFFFFFFu, c, off);
    }
    __shared__ float sa[THREADS / 32], sb[THREADS / 32], sc[THREADS / 32];
    int lane = threadIdx.x & 31;
    int warp = threadIdx.x >> 5;
    if (lane == 0) { sa[warp] = a; sb[warp] = b; sc[warp] = c; }
    __syncthreads();
    if (warp == 0) {
        a = (lane < THREADS / 32) ? sa[lane] : 0.0f;
        b = (lane < THREADS / 32) ? sb[lane] : 0.0f;
        c = (lane < THREADS / 32) ? sc[lane] : 0.0f;
        #pragma unroll
        for (int off = (THREADS / 64); off > 0; off >>= 1) {
            a += __shfl_down_sync(0xFFFFFFFFu, a, off);
            b += __shfl_down_sync(0xFFFFFFFFu, b, off);
            c += __shfl_down_sync(0xFFFFFFFFu, c, off);
        }
    }
}

__global__ void __launch_bounds__(THREADS)
bce_fused_kernel(const float* __restrict__ x_all,
                 const float* __restrict__ t_all,
                 int n_per_sample,
                 float* __restrict__ out)
{
    const int b   = blockIdx.y;
    const int blk = blockIdx.x;

    const float4* __restrict__ x4 =
        reinterpret_cast<const float4*>(x_all + (size_t)b * n_per_sample);
    const float4* __restrict__ t4 =
        reinterpret_cast<const float4*>(t_all + (size_t)b * n_per_sample);
    const int n4 = n_per_sample >> 2;     // 65536
    const int STRIDE = BPB * THREADS;     // 8192 float4s per grid-stride step

    float A = 0.0f;      // Σ relu(x)                (all elements)
    float Bp = 0.0f;     // Σ t * relu(-x)           (pos linear part)
    float Cp = 0.0f;     // Σ t * relu(x)
    float cnt = 0.0f;    // Σ t
    float sp_log = 0.0f; // Σ_pos log(1+e)
    float sn_log = 0.0f; // Σ_neg log(1+e)

    // assumes n4 % (2*STRIDE) == 0  (65536 / 16384 = 4 steps for the real shape)
    for (int i = blk * THREADS + threadIdx.x; i < n4; i += 2 * STRIDE) {
        // batch the 4 wide loads up front -> MLP 4
        float4 xa = x4[i];
        float4 xb = x4[i + STRIDE];
        float4 ta = t4[i];
        float4 tb = t4[i + STRIDE];

        float pp = 1.0f, pn = 1.0f;   // per-step products (8 factors each, <= 256)

        float xs[8] = {xa.x, xa.y, xa.z, xa.w, xb.x, xb.y, xb.z, xb.w};
        float ts[8] = {ta.x, ta.y, ta.z, ta.w, tb.x, tb.y, tb.z, tb.w};
        #pragma unroll
        for (int k = 0; k < 8; k++) {
            float x = xs[k];
            float t = ts[k];                     // exactly 0.0 or 1.0
            float e = __expf(-fabsf(x));         // 1 mul (|.| folded) + EX2
            float u = t * e;
            pp = fmaf(u, pp, pp);                // pp *= (1 + t*e)
            pn = fmaf(e - u, pn, pn);            // pn *= (1 + (1-t)*e)
            float w  = fmaxf(x, 0.0f);
            float wn = fmaxf(-x, 0.0f);
            A   += w;
            Bp   = fmaf(t, wn, Bp);
            Cp   = fmaf(t, w, Cp);
            cnt += t;
        }
        sp_log += __logf(pp);                    // 1 LG2 + mul per 8 elems
        sn_log += __logf(pn);
    }

    float sp = Bp + sp_log;
    float sn = (A - Cp) + sn_log;

    block_reduce3(sp, sn, cnt);

    __shared__ bool am_last;
    if (threadIdx.x == 0) {
        g_part[blk * 192 +   0 + b] = sp;
        g_part[blk * 192 +  64 + b] = sn;
        g_part[blk * 192 + 128 + b] = cnt;
        __threadfence();
        unsigned int t = atomicAdd(&g_ticket, 1u);
        am_last = (t == (unsigned)(NBLOCKS - 1));
    }
    __syncthreads();
    if (!am_last) return;

    // ---- last block: final reduction ----
    float wpos = 0.0f, wneg = 0.0f, cpos = 0.0f, cneg = 0.0f;
    if (threadIdx.x < BATCH) {
        const int bb = threadIdx.x;
        float Sp = 0.0f, Sn = 0.0f, C = 0.0f;
        #pragma unroll
        for (int j = 0; j < BPB; j++) {
            Sp += g_part[j * 192 +   0 + bb];
            Sn += g_part[j * 192 +  64 + bb];
            C  += g_part[j * 192 + 128 + bb];
        }
        float N     = (float)n_per_sample;
        float tmean = C / N;
        wpos = (1.0f - tmean) * Sp;
        wneg = tmean * Sn;
        cpos = C;
        cneg = N - C;
    }

    __shared__ float s0[2], s1[2], s2[2], s3[2];
    #pragma unroll
    for (int off = 16; off > 0; off >>= 1) {
        wpos += __shfl_down_sync(0xFFFFFFFFu, wpos, off);
        wneg += __shfl_down_sync(0xFFFFFFFFu, wneg, off);
        cpos += __shfl_down_sync(0xFFFFFFFFu, cpos, off);
        cneg += __shfl_down_sync(0xFFFFFFFFu, cneg, off);
    }
    int lane = threadIdx.x & 31;
    int warp = threadIdx.x >> 5;
    if (lane == 0 && warp < 2) { s0[warp] = wpos; s1[warp] = wneg; s2[warp] = cpos; s3[warp] = cneg; }
    __syncthreads();
    if (threadIdx.x == 0) {
        float WP = s0[0] + s0[1];
        float WN = s1[0] + s1[1];
        float CP = s2[0] + s2[1];
        float CN = s3[0] + s3[1];
        out[0] = WP / CP + WN / CN;
        g_ticket = 0;   // reset for next graph replay
    }
}

extern "C" void kernel_launch(void* const* d_in, const int* in_sizes, int n_in,
                              void* d_out, int out_size) {
    const float* x = (const float*)d_in[0];
    const float* t = (const float*)d_in[1];
    float* out = (float*)d_out;

    const int total = in_sizes[0];
    const int n_per_sample = total / BATCH;

    dim3 grid(BPB, BATCH);
    bce_fused_kernel<<<grid, THREADS>>>(x, t, n_per_sample, out);
}

// round 5
// speedup vs baseline: 1.0535x; 1.0535x over previous
#include <cuda_runtime.h>
#include <cuda_bf16.h>

// BalancedBCE fused single-kernel, round 4: single-wave grid.
// 1152 CTAs (64 samples x 18) < 1184 residency capacity (8 CTA/SM @ 32 regs)
// -> no wave quantization; every SM stays fully occupied until the end.

#define BATCH   64
#define BPB     18      // blocks per batch sample -> 1152 total (single wave)
#define THREADS 256
#define NBLOCKS (BATCH * BPB)

// layout: g_part[blk*192 + qty*64 + b], qty: 0=S_pos 1=S_neg 2=count
__device__ float g_part[NBLOCKS * 3];
__device__ unsigned int g_ticket = 0;

__device__ __forceinline__ void block_reduce3(float& a, float& b, float& c) {
    #pragma unroll
    for (int off = 16; off > 0; off >>= 1) {
        a += __shfl_down_sync(0xFFFFFFFFu, a, off);
        b += __shfl_down_sync(0xFFFFFFFFu, b, off);
        c += __shfl_down_sync(0xFFFFFFFFu, c, off);
    }
    __shared__ float sa[THREADS / 32], sb[THREADS / 32], sc[THREADS / 32];
    int lane = threadIdx.x & 31;
    int warp = threadIdx.x >> 5;
    if (lane == 0) { sa[warp] = a; sb[warp] = b; sc[warp] = c; }
    __syncthreads();
    if (warp == 0) {
        a = (lane < THREADS / 32) ? sa[lane] : 0.0f;
        b = (lane < THREADS / 32) ? sb[lane] : 0.0f;
        c = (lane < THREADS / 32) ? sc[lane] : 0.0f;
        #pragma unroll
        for (int off = (THREADS / 64); off > 0; off >>= 1) {
            a += __shfl_down_sync(0xFFFFFFFFu, a, off);
            b += __shfl_down_sync(0xFFFFFFFFu, b, off);
            c += __shfl_down_sync(0xFFFFFFFFu, c, off);
        }
    }
}

__global__ void __launch_bounds__(THREADS, 8)
bce_fused_kernel(const float* __restrict__ x_all,
                 const float* __restrict__ t_all,
                 int n_per_sample,
                 float* __restrict__ out)
{
    const int b   = blockIdx.y;
    const int blk = blockIdx.x;

    const float4* __restrict__ x4 =
        reinterpret_cast<const float4*>(x_all + (size_t)b * n_per_sample);
    const float4* __restrict__ t4 =
        reinterpret_cast<const float4*>(t_all + (size_t)b * n_per_sample);
    const int n4 = n_per_sample >> 2;     // 65536 for the real shape
    const int STRIDE = BPB * THREADS;     // 4608

    float A = 0.0f;      // Σ relu(x)                (all elements)
    float Bp = 0.0f;     // Σ t * relu(-x)
    float Cp = 0.0f;     // Σ t * relu(x)
    float cnt = 0.0f;    // Σ t
    float sp_log = 0.0f; // Σ_pos log(1+e)
    float sn_log = 0.0f; // Σ_neg log(1+e)

    for (int i = blk * THREADS + threadIdx.x; i < n4; i += STRIDE) {
        float4 xv = x4[i];
        float4 tv = t4[i];

        float pp = 1.0f, pn = 1.0f;  // 4-factor products, each factor in (1,2]

        float xs[4] = {xv.x, xv.y, xv.z, xv.w};
        float ts[4] = {tv.x, tv.y, tv.z, tv.w};
        #pragma unroll
        for (int k = 0; k < 4; k++) {
            float x = xs[k];
            float t = ts[k];                 // exactly 0.0 or 1.0
            float e = __expf(-fabsf(x));
            float u = t * e;
            pp = fmaf(u, pp, pp);            // pp *= (1 + t*e)
            pn = fmaf(e - u, pn, pn);        // pn *= (1 + (1-t)*e)
            float w  = fmaxf(x, 0.0f);
            float wn = fmaxf(-x, 0.0f);
            A   += w;
            Bp   = fmaf(t, wn, Bp);
            Cp   = fmaf(t, w, Cp);
            cnt += t;
        }
        sp_log += __logf(pp);
        sn_log += __logf(pn);
    }

    float sp = Bp + sp_log;
    float sn = (A - Cp) + sn_log;

    block_reduce3(sp, sn, cnt);

    __shared__ bool am_last;
    if (threadIdx.x == 0) {
        g_part[blk * 192 +   0 + b] = sp;
        g_part[blk * 192 +  64 + b] = sn;
        g_part[blk * 192 + 128 + b] = cnt;
        __threadfence();
        unsigned int t = atomicAdd(&g_ticket, 1u);
        am_last = (t == (unsigned)(NBLOCKS - 1));
    }
    __syncthreads();
    if (!am_last) return;

    // ---- last block: final reduction ----
    float wpos = 0.0f, wneg = 0.0f, cpos = 0.0f, cneg = 0.0f;
    if (threadIdx.x < BATCH) {
        const int bb = threadIdx.x;
        float Sp = 0.0f, Sn = 0.0f, C = 0.0f;
        #pragma unroll
        for (int j = 0; j < BPB; j++) {
            Sp += g_part[j * 192 +   0 + bb];
            Sn += g_part[j * 192 +  64 + bb];
            C  += g_part[j * 192 + 128 + bb];
        }
        float N     = (float)n_per_sample;
        float tmean = C / N;
        wpos = (1.0f - tmean) * Sp;
        wneg = tmean * Sn;
        cpos = C;
        cneg = N - C;
    }

    __shared__ float s0[2], s1[2], s2[2], s3[2];
    #pragma unroll
    for (int off = 16; off > 0; off >>= 1) {
        wpos += __shfl_down_sync(0xFFFFFFFFu, wpos, off);
        wneg += __shfl_down_sync(0xFFFFFFFFu, wneg, off);
        cpos += __shfl_down_sync(0xFFFFFFFFu, cpos, off);
        cneg += __shfl_down_sync(0xFFFFFFFFu, cneg, off);
    }
    int lane = threadIdx.x & 31;
    int warp = threadIdx.x >> 5;
    if (lane == 0 && warp < 2) { s0[warp] = wpos; s1[warp] = wneg; s2[warp] = cpos; s3[warp] = cneg; }
    __syncthreads();
    if (threadIdx.x == 0) {
        float WP = s0[0] + s0[1];
        float WN = s1[0] + s1[1];
        float CP = s2[0] + s2[1];
        float CN = s3[0] + s3[1];
        out[0] = WP / CP + WN / CN;
        g_ticket = 0;   // reset for next graph replay (deterministic)
    }
}

extern "C" void kernel_launch(void* const* d_in, const int* in_sizes, int n_in,
                              void* d_out, int out_size) {
    const float* x = (const float*)d_in[0];
    const float* t = (const float*)d_in[1];
    float* out = (float*)d_out;

    const int total = in_sizes[0];
    const int n_per_sample = total / BATCH;

    dim3 grid(BPB, BATCH);
    bce_fused_kernel<<<grid, THREADS>>>(x, t, n_per_sample, out);
}

// round 6
// speedup vs baseline: 1.0571x; 1.0034x over previous
#include <cuda_runtime.h>
#include <cuda_bf16.h>

// BalancedBCE fused single-kernel, round 5:
//  - 1216 CTAs = exactly 8 CTAs on each of GB300's 152 SMs (perfect balance,
//    single wave at the 32-reg / 8-CTA-per-SM residency point)
//  - unroll x2 with front-batched loads -> 4 LDG.128 in flight per thread

#define BATCH   64
#define BPB     19      // blocks per batch sample -> 64*19 = 1216 = 8 * 152
#define THREADS 256
#define NBLOCKS (BATCH * BPB)

// layout: g_part[blk*192 + qty*64 + b], qty: 0=S_pos 1=S_neg 2=count
__device__ float g_part[NBLOCKS * 3];
__device__ unsigned int g_ticket = 0;

__device__ __forceinline__ void block_reduce3(float& a, float& b, float& c) {
    #pragma unroll
    for (int off = 16; off > 0; off >>= 1) {
        a += __shfl_down_sync(0xFFFFFFFFu, a, off);
        b += __shfl_down_sync(0xFFFFFFFFu, b, off);
        c += __shfl_down_sync(0xFFFFFFFFu, c, off);
    }
    __shared__ float sa[THREADS / 32], sb[THREADS / 32], sc[THREADS / 32];
    int lane = threadIdx.x & 31;
    int warp = threadIdx.x >> 5;
    if (lane == 0) { sa[warp] = a; sb[warp] = b; sc[warp] = c; }
    __syncthreads();
    if (warp == 0) {
        a = (lane < THREADS / 32) ? sa[lane] : 0.0f;
        b = (lane < THREADS / 32) ? sb[lane] : 0.0f;
        c = (lane < THREADS / 32) ? sc[lane] : 0.0f;
        #pragma unroll
        for (int off = (THREADS / 64); off > 0; off >>= 1) {
            a += __shfl_down_sync(0xFFFFFFFFu, a, off);
            b += __shfl_down_sync(0xFFFFFFFFu, b, off);
            c += __shfl_down_sync(0xFFFFFFFFu, c, off);
        }
    }
}

struct Acc {
    float A, Bp, Cp, cnt, sp_log, sn_log;
};

__device__ __forceinline__ void body4(const float4& xv, const float4& tv, Acc& s) {
    float pp = 1.0f, pn = 1.0f;
    float xs[4] = {xv.x, xv.y, xv.z, xv.w};
    float ts[4] = {tv.x, tv.y, tv.z, tv.w};
    #pragma unroll
    for (int k = 0; k < 4; k++) {
        float x = xs[k];
        float t = ts[k];                 // exactly 0.0 or 1.0
        float e = __expf(-fabsf(x));
        float u = t * e;
        pp = fmaf(u, pp, pp);            // pp *= (1 + t*e)
        pn = fmaf(e - u, pn, pn);        // pn *= (1 + (1-t)*e)
        float w  = fmaxf(x, 0.0f);
        float wn = fmaxf(-x, 0.0f);
        s.A   += w;
        s.Bp   = fmaf(t, wn, s.Bp);
        s.Cp   = fmaf(t, w, s.Cp);
        s.cnt += t;
    }
    s.sp_log += __logf(pp);
    s.sn_log += __logf(pn);
}

__global__ void __launch_bounds__(THREADS, 8)
bce_fused_kernel(const float* __restrict__ x_all,
                 const float* __restrict__ t_all,
                 int n_per_sample,
                 float* __restrict__ out)
{
    const int b   = blockIdx.y;
    const int blk = blockIdx.x;

    const float4* __restrict__ x4 =
        reinterpret_cast<const float4*>(x_all + (size_t)b * n_per_sample);
    const float4* __restrict__ t4 =
        reinterpret_cast<const float4*>(t_all + (size_t)b * n_per_sample);
    const int n4 = n_per_sample >> 2;     // 65536 for the real shape
    const int STRIDE = BPB * THREADS;     // 4864

    Acc s = {0.0f, 0.0f, 0.0f, 0.0f, 0.0f, 0.0f};

    int i = blk * THREADS + threadIdx.x;
    // double-step main loop: 4 LDG.128 batched up front (MLP 4)
    for (; i + STRIDE < n4; i += 2 * STRIDE) {
        float4 xa = x4[i];
        float4 xb = x4[i + STRIDE];
        float4 ta = t4[i];
        float4 tb = t4[i + STRIDE];
        body4(xa, ta, s);
        body4(xb, tb, s);
    }
    if (i < n4) {           // ragged tail (threads with 14th iteration)
        float4 xa = x4[i];
        float4 ta = t4[i];
        body4(xa, ta, s);
    }

    float sp = s.Bp + s.sp_log;
    float sn = (s.A - s.Cp) + s.sn_log;
    float cnt = s.cnt;

    block_reduce3(sp, sn, cnt);

    __shared__ bool am_last;
    if (threadIdx.x == 0) {
        g_part[blk * 192 +   0 + b] = sp;
        g_part[blk * 192 +  64 + b] = sn;
        g_part[blk * 192 + 128 + b] = cnt;
        __threadfence();
        unsigned int t = atomicAdd(&g_ticket, 1u);
        am_last = (t == (unsigned)(NBLOCKS - 1));
    }
    __syncthreads();
    if (!am_last) return;

    // ---- last block: final reduction ----
    float wpos = 0.0f, wneg = 0.0f, cpos = 0.0f, cneg = 0.0f;
    if (threadIdx.x < BATCH) {
        const int bb = threadIdx.x;
        float Sp = 0.0f, Sn = 0.0f, C = 0.0f;
        #pragma unroll
        for (int j = 0; j < BPB; j++) {
            Sp += g_part[j * 192 +   0 + bb];
            Sn += g_part[j * 192 +  64 + bb];
            C  += g_part[j * 192 + 128 + bb];
        }
        float N     = (float)n_per_sample;
        float tmean = C / N;
        wpos = (1.0f - tmean) * Sp;
        wneg = tmean * Sn;
        cpos = C;
        cneg = N - C;
    }

    __shared__ float s0[2], s1[2], s2[2], s3[2];
    #pragma unroll
    for (int off = 16; off > 0; off >>= 1) {
        wpos += __shfl_down_sync(0xFFFFFFFFu, wpos, off);
        wneg += __shfl_down_sync(0xFFFFFFFFu, wneg, off);
        cpos += __shfl_down_sync(0xFFFFFFFFu, cpos, off);
        cneg += __shfl_down_sync(0xFFFFFFFFu, cneg, off);
    }
    int lane = threadIdx.x & 31;
    int warp = threadIdx.x >> 5;
    if (lane == 0 && warp < 2) { s0[warp] = wpos; s1[warp] = wneg; s2[warp] = cpos; s3[warp] = cneg; }
    __syncthreads();
    if (threadIdx.x == 0) {
        float WP = s0[0] + s0[1];
        float WN = s1[0] + s1[1];
        float CP = s2[0] + s2[1];
        float CN = s3[0] + s3[1];
        out[0] = WP / CP + WN / CN;
        g_ticket = 0;   // reset for next graph replay (deterministic)
    }
}

extern "C" void kernel_launch(void* const* d_in, const int* in_sizes, int n_in,
                              void* d_out, int out_size) {
    const float* x = (const float*)d_in[0];
    const float* t = (const float*)d_in[1];
    float* out = (float*)d_out;

    const int total = in_sizes[0];
    const int n_per_sample = total / BATCH;

    dim3 grid(BPB, BATCH);
    bce_fused_kernel<<<grid, THREADS>>>(x, t, n_per_sample, out);
}

// round 7
// speedup vs baseline: 1.0818x; 1.0234x over previous
#include <cuda_runtime.h>
#include <cuda_bf16.h>

// BalancedBCE fused single-kernel, round 5:
//  - 1216 CTAs = exactly 8 CTAs on each of GB300's 152 SMs (perfect balance,
//    single wave at the 32-reg / 8-CTA-per-SM residency point)
//  - unroll x2 with front-batched loads -> 4 LDG.128 in flight per thread

#define BATCH   64
#define BPB     19      // blocks per batch sample -> 64*19 = 1216 = 8 * 152
#define THREADS 256
#define NBLOCKS (BATCH * BPB)

// layout: g_part[blk*192 + qty*64 + b], qty: 0=S_pos 1=S_neg 2=count
__device__ float g_part[NBLOCKS * 3];
__device__ unsigned int g_ticket = 0;

__device__ __forceinline__ void block_reduce3(float& a, float& b, float& c) {
    #pragma unroll
    for (int off = 16; off > 0; off >>= 1) {
        a += __shfl_down_sync(0xFFFFFFFFu, a, off);
        b += __shfl_down_sync(0xFFFFFFFFu, b, off);
        c += __shfl_down_sync(0xFFFFFFFFu, c, off);
    }
    __shared__ float sa[THREADS / 32], sb[THREADS / 32], sc[THREADS / 32];
    int lane = threadIdx.x & 31;
    int warp = threadIdx.x >> 5;
    if (lane == 0) { sa[warp] = a; sb[warp] = b; sc[warp] = c; }
    __syncthreads();
    if (warp == 0) {
        a = (lane < THREADS / 32) ? sa[lane] : 0.0f;
        b = (lane < THREADS / 32) ? sb[lane] : 0.0f;
        c = (lane < THREADS / 32) ? sc[lane] : 0.0f;
        #pragma unroll
        for (int off = (THREADS / 64); off > 0; off >>= 1) {
            a += __shfl_down_sync(0xFFFFFFFFu, a, off);
            b += __shfl_down_sync(0xFFFFFFFFu, b, off);
            c += __shfl_down_sync(0xFFFFFFFFu, c, off);
        }
    }
}

struct Acc {
    float A, Bp, Cp, cnt, sp_log, sn_log;
};

__device__ __forceinline__ void body4(const float4& xv, const float4& tv, Acc& s) {
    float pp = 1.0f, pn = 1.0f;
    float xs[4] = {xv.x, xv.y, xv.z, xv.w};
    float ts[4] = {tv.x, tv.y, tv.z, tv.w};
    #pragma unroll
    for (int k = 0; k < 4; k++) {
        float x = xs[k];
        float t = ts[k];                 // exactly 0.0 or 1.0
        float e = __expf(-fabsf(x));
        float u = t * e;
        pp = fmaf(u, pp, pp);            // pp *= (1 + t*e)
        pn = fmaf(e - u, pn, pn);        // pn *= (1 + (1-t)*e)
        float w  = fmaxf(x, 0.0f);
        float wn = fmaxf(-x, 0.0f);
        s.A   += w;
        s.Bp   = fmaf(t, wn, s.Bp);
        s.Cp   = fmaf(t, w, s.Cp);
        s.cnt += t;
    }
    s.sp_log += __logf(pp);
    s.sn_log += __logf(pn);
}

__global__ void __launch_bounds__(THREADS, 8)
bce_fused_kernel(const float* __restrict__ x_all,
                 const float* __restrict__ t_all,
                 int n_per_sample,
                 float* __restrict__ out)
{
    const int b   = blockIdx.y;
    const int blk = blockIdx.x;

    const float4* __restrict__ x4 =
        reinterpret_cast<const float4*>(x_all + (size_t)b * n_per_sample);
    const float4* __restrict__ t4 =
        reinterpret_cast<const float4*>(t_all + (size_t)b * n_per_sample);
    const int n4 = n_per_sample >> 2;     // 65536 for the real shape
    const int STRIDE = BPB * THREADS;     // 4864

    Acc s = {0.0f, 0.0f, 0.0f, 0.0f, 0.0f, 0.0f};

    int i = blk * THREADS + threadIdx.x;
    // double-step main loop: 4 LDG.128 batched up front (MLP 4)
    for (; i + STRIDE < n4; i += 2 * STRIDE) {
        float4 xa = x4[i];
        float4 xb = x4[i + STRIDE];
        float4 ta = t4[i];
        float4 tb = t4[i + STRIDE];
        body4(xa, ta, s);
        body4(xb, tb, s);
    }
    if (i < n4) {           // ragged tail (threads with 14th iteration)
        float4 xa = x4[i];
        float4 ta = t4[i];
        body4(xa, ta, s);
    }

    float sp = s.Bp + s.sp_log;
    float sn = (s.A - s.Cp) + s.sn_log;
    float cnt = s.cnt;

    block_reduce3(sp, sn, cnt);

    __shared__ bool am_last;
    if (threadIdx.x == 0) {
        g_part[blk * 192 +   0 + b] = sp;
        g_part[blk * 192 +  64 + b] = sn;
        g_part[blk * 192 + 128 + b] = cnt;
        __threadfence();
        unsigned int t = atomicAdd(&g_ticket, 1u);
        am_last = (t == (unsigned)(NBLOCKS - 1));
    }
    __syncthreads();
    if (!am_last) return;

    // ---- last block: final reduction ----
    float wpos = 0.0f, wneg = 0.0f, cpos = 0.0f, cneg = 0.0f;
    if (threadIdx.x < BATCH) {
        const int bb = threadIdx.x;
        float Sp = 0.0f, Sn = 0.0f, C = 0.0f;
        #pragma unroll
        for (int j = 0; j < BPB; j++) {
            Sp += g_part[j * 192 +   0 + bb];
            Sn += g_part[j * 192 +  64 + bb];
            C  += g_part[j * 192 + 128 + bb];
        }
        float N     = (float)n_per_sample;
        float tmean = C / N;
        wpos = (1.0f - tmean) * Sp;
        wneg = tmean * Sn;
        cpos = C;
        cneg = N - C;
    }

    __shared__ float s0[2], s1[2], s2[2], s3[2];
    #pragma unroll
    for (int off = 16; off > 0; off >>= 1) {
        wpos += __shfl_down_sync(0xFFFFFFFFu, wpos, off);
        wneg += __shfl_down_sync(0xFFFFFFFFu, wneg, off);
        cpos += __shfl_down_sync(0xFFFFFFFFu, cpos, off);
        cneg += __shfl_down_sync(0xFFFFFFFFu, cneg, off);
    }
    int lane = threadIdx.x & 31;
    int warp = threadIdx.x >> 5;
    if (lane == 0 && warp < 2) { s0[warp] = wpos; s1[warp] = wneg; s2[warp] = cpos; s3[warp] = cneg; }
    __syncthreads();
    if (threadIdx.x == 0) {
        float WP = s0[0] + s0[1];
        float WN = s1[0] + s1[1];
        float CP = s2[0] + s2[1];
        float CN = s3[0] + s3[1];
        out[0] = WP / CP + WN / CN;
        g_ticket = 0;   // reset for next graph replay (deterministic)
    }
}

extern "C" void kernel_launch(void* const* d_in, const int* in_sizes, int n_in,
                              void* d_out, int out_size) {
    const float* x = (const float*)d_in[0];
    const float* t = (const float*)d_in[1];
    float* out = (float*)d_out;

    const int total = in_sizes[0];
    const int n_per_sample = total / BATCH;

    dim3 grid(BPB, BATCH);
    bce_fused_kernel<<<grid, THREADS>>>(x, t, n_per_sample, out);
}

// round 8
// speedup vs baseline: 1.0843x; 1.0023x over previous
#include <cuda_runtime.h>
#include <cuda_bf16.h>

// BalancedBCE fused single-kernel, round 6: 256-bit global loads.
// Theory: L1tex miss queue is entry-count saturated; LDG.256 doubles the
// bytes per outstanding entry -> doubles in-flight bytes -> higher DRAM BW.

#define BATCH   64
#define BPB     14      // 64*14 = 896 CTAs: single wave at 6 or 8 CTA/SM
#define THREADS 256
#define NBLOCKS (BATCH * BPB)

// layout: g_part[blk*192 + qty*64 + b], qty: 0=S_pos 1=S_neg 2=count
__device__ float g_part[NBLOCKS * 3];
__device__ unsigned int g_ticket = 0;

__device__ __forceinline__ void ldg256(const float* __restrict__ p, float r[8]) {
    asm volatile("ld.global.nc.v8.f32 {%0,%1,%2,%3,%4,%5,%6,%7}, [%8];"
                 : "=f"(r[0]), "=f"(r[1]), "=f"(r[2]), "=f"(r[3]),
                   "=f"(r[4]), "=f"(r[5]), "=f"(r[6]), "=f"(r[7])
                 : "l"(p));
}

__device__ __forceinline__ void block_reduce3(float& a, float& b, float& c) {
    #pragma unroll
    for (int off = 16; off > 0; off >>= 1) {
        a += __shfl_down_sync(0xFFFFFFFFu, a, off);
        b += __shfl_down_sync(0xFFFFFFFFu, b, off);
        c += __shfl_down_sync(0xFFFFFFFFu, c, off);
    }
    __shared__ float sa[THREADS / 32], sb[THREADS / 32], sc[THREADS / 32];
    int lane = threadIdx.x & 31;
    int warp = threadIdx.x >> 5;
    if (lane == 0) { sa[warp] = a; sb[warp] = b; sc[warp] = c; }
    __syncthreads();
    if (warp == 0) {
        a = (lane < THREADS / 32) ? sa[lane] : 0.0f;
        b = (lane < THREADS / 32) ? sb[lane] : 0.0f;
        c = (lane < THREADS / 32) ? sc[lane] : 0.0f;
        #pragma unroll
        for (int off = (THREADS / 64); off > 0; off >>= 1) {
            a += __shfl_down_sync(0xFFFFFFFFu, a, off);
            b += __shfl_down_sync(0xFFFFFFFFu, b, off);
            c += __shfl_down_sync(0xFFFFFFFFu, c, off);
        }
    }
}

__global__ void __launch_bounds__(THREADS)
bce_fused_kernel(const float* __restrict__ x_all,
                 const float* __restrict__ t_all,
                 int n_per_sample,
                 float* __restrict__ out)
{
    const int b   = blockIdx.y;
    const int blk = blockIdx.x;

    const float* __restrict__ xs_base = x_all + (size_t)b * n_per_sample;
    const float* __restrict__ ts_base = t_all + (size_t)b * n_per_sample;
    const int n = n_per_sample;                 // 262144
    const int STRIDE = BPB * THREADS * 8;       // 28672 elements

    float A = 0.0f;      // Σ relu(x)
    float Bp = 0.0f;     // Σ t * relu(-x)
    float Cp = 0.0f;     // Σ t * relu(x)
    float cnt = 0.0f;    // Σ t
    float sp_log = 0.0f; // Σ_pos log(1+e)
    float sn_log = 0.0f; // Σ_neg log(1+e)

    int i = (blk * THREADS + threadIdx.x) * 8;
    for (; i + 8 <= n; i += STRIDE) {
        float xv[8], tv[8];
        ldg256(xs_base + i, xv);     // two 256-bit entries in flight
        ldg256(ts_base + i, tv);

        float pp = 1.0f, pn = 1.0f;  // 8 factors each, in (1,2] -> <= 256
        #pragma unroll
        for (int k = 0; k < 8; k++) {
            float x = xv[k];
            float t = tv[k];                 // exactly 0.0 or 1.0
            float e = __expf(-fabsf(x));
            float u = t * e;
            pp = fmaf(u, pp, pp);            // *= (1 + t*e)
            pn = fmaf(e - u, pn, pn);        // *= (1 + (1-t)*e)
            float w  = fmaxf(x, 0.0f);
            float wn = fmaxf(-x, 0.0f);
            A   += w;
            Bp   = fmaf(t, wn, Bp);
            Cp   = fmaf(t, w, Cp);
            cnt += t;
        }
        sp_log += __logf(pp);
        sn_log += __logf(pn);
    }
    // scalar tail (does not execute for the real 262144-element shape)
    for (; i < n; i++) {
        float x = xs_base[i];
        float t = ts_base[i];
        float e = __expf(-fabsf(x));
        float l = __logf(1.0f + e);
        float w  = fmaxf(x, 0.0f);
        float wn = fmaxf(-x, 0.0f);
        A   += w;
        Bp   = fmaf(t, wn, Bp);
        Cp   = fmaf(t, w, Cp);
        cnt += t;
        sp_log += t * l;
        sn_log += (1.0f - t) * l;
    }

    float sp = Bp + sp_log;
    float sn = (A - Cp) + sn_log;

    block_reduce3(sp, sn, cnt);

    __shared__ bool am_last;
    if (threadIdx.x == 0) {
        g_part[blk * 192 +   0 + b] = sp;
        g_part[blk * 192 +  64 + b] = sn;
        g_part[blk * 192 + 128 + b] = cnt;
        __threadfence();
        unsigned int t = atomicAdd(&g_ticket, 1u);
        am_last = (t == (unsigned)(NBLOCKS - 1));
    }
    __syncthreads();
    if (!am_last) return;

    // ---- last block: final reduction ----
    float wpos = 0.0f, wneg = 0.0f, cpos = 0.0f, cneg = 0.0f;
    if (threadIdx.x < BATCH) {
        const int bb = threadIdx.x;
        float Sp = 0.0f, Sn = 0.0f, C = 0.0f;
        #pragma unroll
        for (int j = 0; j < BPB; j++) {
            Sp += g_part[j * 192 +   0 + bb];
            Sn += g_part[j * 192 +  64 + bb];
            C  += g_part[j * 192 + 128 + bb];
        }
        float N     = (float)n_per_sample;
        float tmean = C / N;
        wpos = (1.0f - tmean) * Sp;
        wneg = tmean * Sn;
        cpos = C;
        cneg = N - C;
    }

    __shared__ float s0[2], s1[2], s2[2], s3[2];
    #pragma unroll
    for (int off = 16; off > 0; off >>= 1) {
        wpos += __shfl_down_sync(0xFFFFFFFFu, wpos, off);
        wneg += __shfl_down_sync(0xFFFFFFFFu, wneg, off);
        cpos += __shfl_down_sync(0xFFFFFFFFu, cpos, off);
        cneg += __shfl_down_sync(0xFFFFFFFFu, cneg, off);
    }
    int lane = threadIdx.x & 31;
    int warp = threadIdx.x >> 5;
    if (lane == 0 && warp < 2) { s0[warp] = wpos; s1[warp] = wneg; s2[warp] = cpos; s3[warp] = cneg; }
    __syncthreads();
    if (threadIdx.x == 0) {
        float WP = s0[0] + s0[1];
        float WN = s1[0] + s1[1];
        float CP = s2[0] + s2[1];
        float CN = s3[0] + s3[1];
        out[0] = WP / CP + WN / CN;
        g_ticket = 0;   // reset for next graph replay (deterministic)
    }
}

extern "C" void kernel_launch(void* const* d_in, const int* in_sizes, int n_in,
                              void* d_out, int out_size) {
    const float* x = (const float*)d_in[0];
    const float* t = (const float*)d_in[1];
    float* out = (float*)d_out;

    const int total = in_sizes[0];
    const int n_per_sample = total / BATCH;

    dim3 grid(BPB, BATCH);
    bce_fused_kernel<<<grid, THREADS>>>(x, t, n_per_sample, out);
}